// round 2
// baseline (speedup 1.0000x reference)
#include <cuda_runtime.h>
#include <math.h>

#define BATCH 256
#define HID   1024
#define H3    3072
#define VOC   512
#define TT    256
#define FPD   2048

// ---------------- scratch (__device__ globals; no allocation allowed) ----------------
__device__ float g_h0[2][BATCH * HID];
__device__ float g_h1[2][BATCH * HID];
__device__ float g_G0[VOC * H3];          // relu(emb) @ W_ih0^T + b_ih0, per-token gate table
__device__ float g_gh1[BATCH * H3];       // h1_prev @ W_hh1^T + b_hh1
__device__ float g_Hbuf[(size_t)TT * BATCH * HID];  // all h1 states for deferred output GEMM

// ---------------- helpers ----------------
__device__ __forceinline__ unsigned f2tf(float f) {
    unsigned u;
    asm("cvt.rna.tf32.f32 %0, %1;" : "=r"(u) : "f"(f));
    return u;
}

__device__ __forceinline__ void mma8(float c[4], const unsigned a[4], const unsigned b[2]) {
    asm volatile(
        "mma.sync.aligned.m16n8k8.row.col.f32.tf32.tf32.f32 "
        "{%0,%1,%2,%3},{%4,%5,%6,%7},{%8,%9},{%0,%1,%2,%3};"
        : "+f"(c[0]), "+f"(c[1]), "+f"(c[2]), "+f"(c[3])
        : "r"(a[0]), "r"(a[1]), "r"(a[2]), "r"(a[3]), "r"(b[0]), "r"(b[1]));
}

__device__ __forceinline__ float sigm(float x) { return 1.0f / (1.0f + __expf(-x)); }

// ---------------- plain 64x64 GEMM core: C[m,n] = sum_k A[m,k]*W[n,k] ----------------
// 256 threads, 8 warps as 2(M) x 4(N); warp tile 32x16; BK=32.
__device__ __forceinline__ void gemm64x64(const float* A, int lda, const float* W, int ldw,
                                          int K, int m0, int n0, int reluA,
                                          unsigned* As, unsigned* Bs, float c[2][2][4]) {
    const int tid = threadIdx.x, lane = tid & 31, wid = tid >> 5;
    const int g = lane >> 2, t4 = lane & 3;
    const int warpM = wid >> 2, warpN = wid & 3;

    for (int kk = 0; kk < K; kk += 32) {
#pragma unroll
        for (int p = 0; p < 2; p++) {
            int r = p * 32 + (tid >> 3);
            int c4 = (tid & 7) * 4;
            float4 v = *(const float4*)(A + (size_t)(m0 + r) * lda + kk + c4);
            if (reluA) { v.x = fmaxf(v.x, 0.f); v.y = fmaxf(v.y, 0.f); v.z = fmaxf(v.z, 0.f); v.w = fmaxf(v.w, 0.f); }
            unsigned* d = As + r * 36 + c4;
            d[0] = f2tf(v.x); d[1] = f2tf(v.y); d[2] = f2tf(v.z); d[3] = f2tf(v.w);
            float4 w = *(const float4*)(W + (size_t)(n0 + r) * ldw + kk + c4);
            unsigned* e = Bs + r * 36 + c4;
            e[0] = f2tf(w.x); e[1] = f2tf(w.y); e[2] = f2tf(w.z); e[3] = f2tf(w.w);
        }
        __syncthreads();
#pragma unroll
        for (int ks = 0; ks < 4; ks++) {
            int kb = ks * 8;
            unsigned a[2][4], b[2][2];
#pragma unroll
            for (int mt = 0; mt < 2; mt++) {
                int row = warpM * 32 + mt * 16 + g;
                a[mt][0] = As[row * 36 + kb + t4];
                a[mt][1] = As[(row + 8) * 36 + kb + t4];
                a[mt][2] = As[row * 36 + kb + t4 + 4];
                a[mt][3] = As[(row + 8) * 36 + kb + t4 + 4];
            }
#pragma unroll
            for (int nt = 0; nt < 2; nt++) {
                int nr = warpN * 16 + nt * 8 + g;
                b[nt][0] = Bs[nr * 36 + kb + t4];
                b[nt][1] = Bs[nr * 36 + kb + t4 + 4];
            }
#pragma unroll
            for (int mt = 0; mt < 2; mt++)
#pragma unroll
                for (int nt = 0; nt < 2; nt++) mma8(c[mt][nt], a[mt], b[nt]);
        }
        __syncthreads();
    }
}

// ---------------- triple-gate 64x(3x32) GEMM core over K=HID ----------------
// Computes, for j in [jb, jb+32): acc[g3] = A[m,:] . W[g3*HID + j, :]  (g3 = r/z/n gate)
// 256 threads, 8 warps as 4(M) x 2(Nj); warp tile 16 x 16 per gate.
__device__ __forceinline__ void gemm_triple(const float* A, const float* W, int m0, int jb,
                                            unsigned* As, unsigned* Bs, float c[3][2][4]) {
    const int tid = threadIdx.x, lane = tid & 31, wid = tid >> 5;
    const int g = lane >> 2, t4 = lane & 3;
    const int warpM = wid & 3, warpN = wid >> 2;

    for (int kk = 0; kk < HID; kk += 32) {
#pragma unroll
        for (int p = 0; p < 2; p++) {
            int r = p * 32 + (tid >> 3);
            int c4 = (tid & 7) * 4;
            float4 v = *(const float4*)(A + (size_t)(m0 + r) * HID + kk + c4);
            unsigned* d = As + r * 36 + c4;
            d[0] = f2tf(v.x); d[1] = f2tf(v.y); d[2] = f2tf(v.z); d[3] = f2tf(v.w);
        }
        {
            int r = tid >> 3;
            int c4 = (tid & 7) * 4;
#pragma unroll
            for (int g3 = 0; g3 < 3; g3++) {
                float4 w = *(const float4*)(W + (size_t)(g3 * HID + jb + r) * HID + kk + c4);
                unsigned* e = Bs + g3 * 1152 + r * 36 + c4;
                e[0] = f2tf(w.x); e[1] = f2tf(w.y); e[2] = f2tf(w.z); e[3] = f2tf(w.w);
            }
        }
        __syncthreads();
#pragma unroll
        for (int ks = 0; ks < 4; ks++) {
            int kb = ks * 8;
            unsigned a[4];
            int row = warpM * 16 + g;
            a[0] = As[row * 36 + kb + t4];
            a[1] = As[(row + 8) * 36 + kb + t4];
            a[2] = As[row * 36 + kb + t4 + 4];
            a[3] = As[(row + 8) * 36 + kb + t4 + 4];
#pragma unroll
            for (int g3 = 0; g3 < 3; g3++) {
#pragma unroll
                for (int nt = 0; nt < 2; nt++) {
                    unsigned b[2];
                    int nr = warpN * 16 + nt * 8 + g;
                    b[0] = Bs[g3 * 1152 + nr * 36 + kb + t4];
                    b[1] = Bs[g3 * 1152 + nr * 36 + kb + t4 + 4];
                    mma8(c[g3][nt], a, b);
                }
            }
        }
        __syncthreads();
    }
}

// ---------------- kernels ----------------

// h0 = relu(fingerprints @ Wc^T + bc), replicated into both layer states (buffer 0)
__global__ __launch_bounds__(256) void k_init_h0(const float* fp, const float* Wc, const float* bc) {
    __shared__ unsigned As[64 * 36], Bs[64 * 36];
    float c[2][2][4] = {};
    int n0 = blockIdx.x * 64, m0 = blockIdx.y * 64;
    gemm64x64(fp, FPD, Wc, FPD, FPD, m0, n0, 0, As, Bs, c);
    const int tid = threadIdx.x, lane = tid & 31, wid = tid >> 5;
    const int g = lane >> 2, t4 = lane & 3;
    const int warpM = wid >> 2, warpN = wid & 3;
#pragma unroll
    for (int mt = 0; mt < 2; mt++)
#pragma unroll
        for (int nt = 0; nt < 2; nt++)
#pragma unroll
            for (int ci = 0; ci < 4; ci++) {
                int m = m0 + warpM * 32 + mt * 16 + g + ((ci & 2) ? 8 : 0);
                int n = n0 + warpN * 16 + nt * 8 + t4 * 2 + (ci & 1);
                float v = fmaxf(c[mt][nt][ci] + bc[n], 0.f);
                g_h0[0][m * HID + n] = v;
                g_h1[0][m * HID + n] = v;
            }
}

// G0[v, :] = relu(emb[v,:]) @ W_ih0^T + b_ih0
__global__ __launch_bounds__(256) void k_init_G0(const float* emb, const float* Wih, const float* bih) {
    __shared__ unsigned As[64 * 36], Bs[64 * 36];
    float c[2][2][4] = {};
    int n0 = blockIdx.x * 64, m0 = blockIdx.y * 64;
    gemm64x64(emb, HID, Wih, HID, HID, m0, n0, 1, As, Bs, c);
    const int tid = threadIdx.x, lane = tid & 31, wid = tid >> 5;
    const int g = lane >> 2, t4 = lane & 3;
    const int warpM = wid >> 2, warpN = wid & 3;
#pragma unroll
    for (int mt = 0; mt < 2; mt++)
#pragma unroll
        for (int nt = 0; nt < 2; nt++)
#pragma unroll
            for (int ci = 0; ci < 4; ci++) {
                int m = m0 + warpM * 32 + mt * 16 + g + ((ci & 2) ? 8 : 0);
                int n = n0 + warpN * 16 + nt * 8 + t4 * 2 + (ci & 1);
                g_G0[m * H3 + n] = c[mt][nt][ci] + bih[n];
            }
}

// Step kernel A:
//  z==0: gh0 = h0_prev @ W_hh0^T + b_hh0 ; fuse layer-0 gates with G0[token] -> h0_new
//  z==1: gh1 = h1_prev @ W_hh1^T + b_hh1 -> g_gh1 (plain store)
__global__ __launch_bounds__(256) void k_stepA(int t, const int* tgt, const float* Whh, const float* bhh) {
    __shared__ unsigned As[64 * 36], Bs[3 * 32 * 36];
    const int layer = blockIdx.z;
    const float* h0_in = g_h0[t & 1];
    const float* h1_in = g_h1[t & 1];
    float* h0_out = g_h0[(t + 1) & 1];
    const float* A = layer ? h1_in : h0_in;
    const float* W = Whh + (size_t)layer * H3 * HID;
    const float* bh = bhh + layer * H3;
    int m0 = blockIdx.y * 64, jb = blockIdx.x * 32;
    float c[3][2][4] = {};
    gemm_triple(A, W, m0, jb, As, Bs, c);

    const int tid = threadIdx.x, lane = tid & 31, wid = tid >> 5;
    const int g = lane >> 2, t4 = lane & 3;
    const int warpM = wid & 3, warpN = wid >> 2;
#pragma unroll
    for (int nt = 0; nt < 2; nt++)
#pragma unroll
        for (int ci = 0; ci < 4; ci++) {
            int m = m0 + warpM * 16 + g + ((ci & 2) ? 8 : 0);
            int j = jb + warpN * 16 + nt * 8 + t4 * 2 + (ci & 1);
            float ghr = c[0][nt][ci] + bh[j];
            float ghz = c[1][nt][ci] + bh[HID + j];
            float ghn = c[2][nt][ci] + bh[2 * HID + j];
            if (layer == 0) {
                int tok = (t == 0) ? 0 : tgt[m * TT + t - 1];
                const float* grow = g_G0 + (size_t)tok * H3;
                float r = sigm(grow[j] + ghr);
                float z = sigm(grow[HID + j] + ghz);
                float n = tanhf(grow[2 * HID + j] + r * ghn);
                float hp = h0_in[m * HID + j];
                h0_out[m * HID + j] = (1.0f - z) * n + z * hp;
            } else {
                g_gh1[m * H3 + j] = ghr;
                g_gh1[m * H3 + HID + j] = ghz;
                g_gh1[m * H3 + 2 * HID + j] = ghn;
            }
        }
}

// Step kernel B: gi1 = h0_new @ W_ih1^T + b_ih1 ; fuse layer-1 gates with g_gh1 -> h1_new, store to Hbuf
__global__ __launch_bounds__(256) void k_stepB(int t, const float* Wih, const float* bih) {
    __shared__ unsigned As[64 * 36], Bs[3 * 32 * 36];
    const float* h0n = g_h0[(t + 1) & 1];
    const float* h1_in = g_h1[t & 1];
    float* h1_out = g_h1[(t + 1) & 1];
    const float* W = Wih + (size_t)H3 * HID;  // layer 1
    const float* bi = bih + H3;
    int m0 = blockIdx.y * 64, jb = blockIdx.x * 32;
    float c[3][2][4] = {};
    gemm_triple(h0n, W, m0, jb, As, Bs, c);

    const int tid = threadIdx.x, lane = tid & 31, wid = tid >> 5;
    const int g = lane >> 2, t4 = lane & 3;
    const int warpM = wid & 3, warpN = wid >> 2;
#pragma unroll
    for (int nt = 0; nt < 2; nt++)
#pragma unroll
        for (int ci = 0; ci < 4; ci++) {
            int m = m0 + warpM * 16 + g + ((ci & 2) ? 8 : 0);
            int j = jb + warpN * 16 + nt * 8 + t4 * 2 + (ci & 1);
            float gir = c[0][nt][ci] + bi[j];
            float giz = c[1][nt][ci] + bi[HID + j];
            float gin = c[2][nt][ci] + bi[2 * HID + j];
            float r = sigm(gir + g_gh1[m * H3 + j]);
            float z = sigm(giz + g_gh1[m * H3 + HID + j]);
            float n = tanhf(gin + r * g_gh1[m * H3 + 2 * HID + j]);
            float hp = h1_in[m * HID + j];
            float hn = (1.0f - z) * n + z * hp;
            h1_out[m * HID + j] = hn;
            g_Hbuf[(size_t)t * BATCH * HID + (size_t)m * HID + j] = hn;
        }
}

// logits = Hbuf @ Wo^T + bo, written to out at [b, t, v]  (Hbuf rows are t*B+b)
__global__ __launch_bounds__(256) void k_logits(const float* Wo, const float* bo, float* out) {
    __shared__ unsigned As[64 * 36], Bs[64 * 36];
    float c[2][2][4] = {};
    int n0 = blockIdx.x * 64, m0 = blockIdx.y * 64;
    gemm64x64(g_Hbuf, HID, Wo, HID, HID, m0, n0, 0, As, Bs, c);
    const int tid = threadIdx.x, lane = tid & 31, wid = tid >> 5;
    const int g = lane >> 2, t4 = lane & 3;
    const int warpM = wid >> 2, warpN = wid & 3;
#pragma unroll
    for (int mt = 0; mt < 2; mt++)
#pragma unroll
        for (int nt = 0; nt < 2; nt++)
#pragma unroll
            for (int ci = 0; ci < 4; ci++) {
                int m = m0 + warpM * 32 + mt * 16 + g + ((ci & 2) ? 8 : 0);
                int n = n0 + warpN * 16 + nt * 8 + t4 * 2 + (ci & 1);
                int bb = m & (BATCH - 1);
                int tt = m >> 8;
                out[((size_t)bb * TT + tt) * VOC + n] = c[mt][nt][ci] + bo[n];
            }
}

// in-place log_softmax over the last dim (V=512), one block (128 thr) per row
__global__ __launch_bounds__(128) void k_lsm(float* out) {
    float* p = out + (size_t)blockIdx.x * VOC;
    const int tid = threadIdx.x, lane = tid & 31, wid = tid >> 5;
    __shared__ float smx[4], ssm[4];
    float v[4];
#pragma unroll
    for (int i = 0; i < 4; i++) v[i] = p[tid + 128 * i];
    float mx = fmaxf(fmaxf(v[0], v[1]), fmaxf(v[2], v[3]));
#pragma unroll
    for (int o = 16; o; o >>= 1) mx = fmaxf(mx, __shfl_xor_sync(0xffffffffu, mx, o));
    if (lane == 0) smx[wid] = mx;
    __syncthreads();
    mx = fmaxf(fmaxf(smx[0], smx[1]), fmaxf(smx[2], smx[3]));
    float s = 0.f;
#pragma unroll
    for (int i = 0; i < 4; i++) s += __expf(v[i] - mx);
#pragma unroll
    for (int o = 16; o; o >>= 1) s += __shfl_xor_sync(0xffffffffu, s, o);
    if (lane == 0) ssm[wid] = s;
    __syncthreads();
    s = ssm[0] + ssm[1] + ssm[2] + ssm[3];
    float lse = mx + logf(s);
#pragma unroll
    for (int i = 0; i < 4; i++) p[tid + 128 * i] = v[i] - lse;
}

// copy final hidden states [L,B,H] to the tail of out (after 256 steps, state is in buffer 0)
__global__ __launch_bounds__(512) void k_hfinal(float* outh) {
    int i = blockIdx.x * blockDim.x + threadIdx.x;
    if (i < BATCH * HID) outh[i] = g_h0[0][i];
    else outh[i] = g_h1[0][i - BATCH * HID];
}

// ---------------- launch ----------------
extern "C" void kernel_launch(void* const* d_in, const int* in_sizes, int n_in,
                              void* d_out, int out_size) {
    (void)in_sizes; (void)n_in; (void)out_size;
    const float* fp   = (const float*)d_in[1];
    const int*   tgt  = (const int*)d_in[2];
    const float* emb  = (const float*)d_in[3];
    const float* Wc   = (const float*)d_in[4];
    const float* bc   = (const float*)d_in[5];
    const float* W_ih = (const float*)d_in[6];
    const float* W_hh = (const float*)d_in[7];
    const float* b_ih = (const float*)d_in[8];
    const float* b_hh = (const float*)d_in[9];
    const float* Wo   = (const float*)d_in[10];
    const float* bo   = (const float*)d_in[11];
    float* out = (float*)d_out;

    k_init_h0<<<dim3(16, 4), 256>>>(fp, Wc, bc);
    k_init_G0<<<dim3(48, 8), 256>>>(emb, W_ih, b_ih);
    for (int t = 0; t < TT; t++) {
        k_stepA<<<dim3(32, 4, 2), 256>>>(t, tgt, W_hh, b_hh);
        k_stepB<<<dim3(32, 4), 256>>>(t, W_ih, b_ih);
    }
    k_logits<<<dim3(8, 1024), 256>>>(Wo, bo, out);
    k_lsm<<<65536, 128>>>(out);
    k_hfinal<<<1024, 512>>>(out + (size_t)BATCH * TT * VOC);
}

// round 3
// speedup vs baseline: 1.8275x; 1.8275x over previous
#include <cuda_runtime.h>
#include <cuda_fp16.h>
#include <math.h>

#define BATCH 256
#define HID   1024
#define H3    3072
#define VOC   512
#define TT    256
#define FPD   2048
#define WH    (H3 * HID)
#define NB    128

// ---------------- device scratch ----------------
__device__ __align__(256) float  g_h0[2][BATCH * HID];
__device__ __align__(256) float  g_h1[2][BATCH * HID];
__device__ __align__(256) __half g_h0h[2][BATCH * HID];
__device__ __align__(256) __half g_h1h[2][BATCH * HID];
__device__ __align__(256) float  g_G0[VOC * H3];
__device__ __align__(256) float  g_gh1[BATCH * H3];
__device__ __align__(256) __half g_Whh_h[2][WH];
__device__ __align__(256) __half g_Wih1_h[WH];
__device__ __align__(256) __half g_Wo_h[VOC * HID];
__device__ __align__(256) __half g_Hbufh[(size_t)TT * BATCH * HID];
__device__ unsigned g_bar_count = 0;
__device__ unsigned g_bar_gen   = 0;

// ---------------- helpers ----------------
__device__ __forceinline__ unsigned f2tf(float f) {
    unsigned u; asm("cvt.rna.tf32.f32 %0, %1;" : "=r"(u) : "f"(f)); return u;
}
__device__ __forceinline__ void mma8(float c[4], const unsigned a[4], const unsigned b[2]) {
    asm volatile("mma.sync.aligned.m16n8k8.row.col.f32.tf32.tf32.f32 "
                 "{%0,%1,%2,%3},{%4,%5,%6,%7},{%8,%9},{%0,%1,%2,%3};"
                 : "+f"(c[0]), "+f"(c[1]), "+f"(c[2]), "+f"(c[3])
                 : "r"(a[0]), "r"(a[1]), "r"(a[2]), "r"(a[3]), "r"(b[0]), "r"(b[1]));
}
__device__ __forceinline__ void mmah(float c[4], const unsigned a[4], const unsigned b[2]) {
    asm volatile("mma.sync.aligned.m16n8k16.row.col.f32.f16.f16.f32 "
                 "{%0,%1,%2,%3},{%4,%5,%6,%7},{%8,%9},{%0,%1,%2,%3};"
                 : "+f"(c[0]), "+f"(c[1]), "+f"(c[2]), "+f"(c[3])
                 : "r"(a[0]), "r"(a[1]), "r"(a[2]), "r"(a[3]), "r"(b[0]), "r"(b[1]));
}
__device__ __forceinline__ float sigm(float x) { return 1.0f / (1.0f + __expf(-x)); }
__device__ __forceinline__ void cpa16(const __half* dst, const __half* src) {
    unsigned d = (unsigned)__cvta_generic_to_shared(dst);
    asm volatile("cp.async.cg.shared.global [%0], [%1], 16;" :: "r"(d), "l"(src));
}
__device__ __forceinline__ void cpcommit() { asm volatile("cp.async.commit_group;"); }
__device__ __forceinline__ void cpwait1()  { asm volatile("cp.async.wait_group 1;"); }
__device__ __forceinline__ void cpwait0()  { asm volatile("cp.async.wait_group 0;"); }
__device__ __forceinline__ float ldcg(const float* p) {
    float v; asm volatile("ld.global.cg.f32 %0, [%1];" : "=f"(v) : "l"(p)); return v;
}
__device__ __forceinline__ void gbarrier() {
    __threadfence();
    __syncthreads();
    if (threadIdx.x == 0) {
        unsigned gen = *((volatile unsigned*)&g_bar_gen);
        if (atomicAdd(&g_bar_count, 1u) == NB - 1) {
            g_bar_count = 0;
            __threadfence();
            atomicAdd(&g_bar_gen, 1u);
        } else {
            while (*((volatile unsigned*)&g_bar_gen) == gen) { __nanosleep(32); }
        }
    }
    __syncthreads();
}

// ---------------- tf32 64x64 GEMM (init kernels only) ----------------
__device__ __forceinline__ void gemm64x64(const float* A, int lda, const float* W, int ldw,
                                          int K, int m0, int n0, int reluA,
                                          unsigned* As, unsigned* Bs, float c[2][2][4]) {
    const int tid = threadIdx.x, lane = tid & 31, wid = tid >> 5;
    const int g = lane >> 2, t4 = lane & 3;
    const int warpM = wid >> 2, warpN = wid & 3;
    for (int kk = 0; kk < K; kk += 32) {
#pragma unroll
        for (int p = 0; p < 2; p++) {
            int r = p * 32 + (tid >> 3), c4 = (tid & 7) * 4;
            float4 v = *(const float4*)(A + (size_t)(m0 + r) * lda + kk + c4);
            if (reluA) { v.x = fmaxf(v.x, 0.f); v.y = fmaxf(v.y, 0.f); v.z = fmaxf(v.z, 0.f); v.w = fmaxf(v.w, 0.f); }
            unsigned* d = As + r * 36 + c4;
            d[0] = f2tf(v.x); d[1] = f2tf(v.y); d[2] = f2tf(v.z); d[3] = f2tf(v.w);
            float4 w = *(const float4*)(W + (size_t)(n0 + r) * ldw + kk + c4);
            unsigned* e = Bs + r * 36 + c4;
            e[0] = f2tf(w.x); e[1] = f2tf(w.y); e[2] = f2tf(w.z); e[3] = f2tf(w.w);
        }
        __syncthreads();
#pragma unroll
        for (int ks = 0; ks < 4; ks++) {
            int kb = ks * 8;
            unsigned a[2][4], b[2][2];
#pragma unroll
            for (int mt = 0; mt < 2; mt++) {
                int row = warpM * 32 + mt * 16 + g;
                a[mt][0] = As[row * 36 + kb + t4];
                a[mt][1] = As[(row + 8) * 36 + kb + t4];
                a[mt][2] = As[row * 36 + kb + t4 + 4];
                a[mt][3] = As[(row + 8) * 36 + kb + t4 + 4];
            }
#pragma unroll
            for (int nt = 0; nt < 2; nt++) {
                int nr = warpN * 16 + nt * 8 + g;
                b[nt][0] = Bs[nr * 36 + kb + t4];
                b[nt][1] = Bs[nr * 36 + kb + t4 + 4];
            }
#pragma unroll
            for (int mt = 0; mt < 2; mt++)
#pragma unroll
                for (int nt = 0; nt < 2; nt++) mma8(c[mt][nt], a[mt], b[nt]);
        }
        __syncthreads();
    }
}

__global__ __launch_bounds__(256) void k_init_h0(const float* fp, const float* Wc, const float* bc) {
    __shared__ unsigned As[64 * 36], Bs[64 * 36];
    float c[2][2][4] = {};
    int n0 = blockIdx.x * 64, m0 = blockIdx.y * 64;
    gemm64x64(fp, FPD, Wc, FPD, FPD, m0, n0, 0, As, Bs, c);
    const int tid = threadIdx.x, lane = tid & 31, wid = tid >> 5;
    const int g = lane >> 2, t4 = lane & 3;
    const int warpM = wid >> 2, warpN = wid & 3;
#pragma unroll
    for (int mt = 0; mt < 2; mt++)
#pragma unroll
        for (int nt = 0; nt < 2; nt++)
#pragma unroll
            for (int ci = 0; ci < 4; ci++) {
                int m = m0 + warpM * 32 + mt * 16 + g + ((ci & 2) ? 8 : 0);
                int n = n0 + warpN * 16 + nt * 8 + t4 * 2 + (ci & 1);
                float v = fmaxf(c[mt][nt][ci] + bc[n], 0.f);
                g_h0[0][m * HID + n] = v;
                g_h1[0][m * HID + n] = v;
                __half vh = __float2half_rn(v);
                g_h0h[0][m * HID + n] = vh;
                g_h1h[0][m * HID + n] = vh;
            }
}

__global__ __launch_bounds__(256) void k_init_G0(const float* emb, const float* Wih, const float* bih) {
    __shared__ unsigned As[64 * 36], Bs[64 * 36];
    float c[2][2][4] = {};
    int n0 = blockIdx.x * 64, m0 = blockIdx.y * 64;
    gemm64x64(emb, HID, Wih, HID, HID, m0, n0, 1, As, Bs, c);
    const int tid = threadIdx.x, lane = tid & 31, wid = tid >> 5;
    const int g = lane >> 2, t4 = lane & 3;
    const int warpM = wid >> 2, warpN = wid & 3;
#pragma unroll
    for (int mt = 0; mt < 2; mt++)
#pragma unroll
        for (int nt = 0; nt < 2; nt++)
#pragma unroll
            for (int ci = 0; ci < 4; ci++) {
                int m = m0 + warpM * 32 + mt * 16 + g + ((ci & 2) ? 8 : 0);
                int n = n0 + warpN * 16 + nt * 8 + t4 * 2 + (ci & 1);
                g_G0[m * H3 + n] = c[mt][nt][ci] + bih[n];
            }
}

__global__ __launch_bounds__(256) void k_convW(const float* Whh, const float* Wih, const float* Wo) {
    size_t i = (size_t)blockIdx.x * blockDim.x + threadIdx.x;
    size_t stride = (size_t)gridDim.x * blockDim.x;
    __half* whh = &g_Whh_h[0][0];
    for (size_t k = i; k < 2 * (size_t)WH; k += stride) whh[k] = __float2half_rn(Whh[k]);
    for (size_t k = i; k < (size_t)WH; k += stride) g_Wih1_h[k] = __float2half_rn(Wih[WH + k]);
    for (size_t k = i; k < (size_t)VOC * HID; k += stride) g_Wo_h[k] = __float2half_rn(Wo[k]);
}

// ---------------- persistent recurrent kernel ----------------
// 128 CTAs x 256 thr. Per step:
//  phase1: bid<64: layer0 gh0 + fused GRU -> h0_new ; bid>=64: layer1 gh1 -> g_gh1
//  phase2: gi1 = h0_new @ Wih1^T + fused GRU layer1 -> h1_new (+fp16 history)
__global__ __launch_bounds__(256, 1) void k_loop(const int* __restrict__ tgt,
                                                 const float* __restrict__ b_ih,
                                                 const float* __restrict__ b_hh) {
    __shared__ __align__(16) unsigned sA[2][128 * 20];   // 128 rows x 32 halves (pad 40)
    __shared__ __align__(16) unsigned sW[2][96 * 20];
    const int tid = threadIdx.x, lane = tid & 31, wid = tid >> 5;
    const int t4 = lane & 3, g8 = lane >> 2;
    const int warpM = wid & 3, warpJ = wid >> 2;
    const int bid = blockIdx.x;
    const int sel = bid >> 6;
    const int m0p1 = ((bid >> 5) & 1) * 128;
    const int m0p2 = (bid >> 5) * 64;
    const int jb = (bid & 31) * 32;
    const float* bh = b_hh + sel * H3;
    const float* bi1 = b_ih + H3;
    const __half* Wp1 = g_Whh_h[sel];
    const int arow = tid >> 2, aseg = tid & 3;
    __half* sAh0 = (__half*)&sA[0][0];
    __half* sAh1 = (__half*)&sA[1][0];
    __half* sWh0 = (__half*)&sW[0][0];
    __half* sWh1 = (__half*)&sW[1][0];

    for (int t = 0; t < TT; t++) {
        const int cur = t & 1, nxt = cur ^ 1;
        // ===== phase 1 =====
        {
            const __half* Ah = sel ? g_h1h[cur] : g_h0h[cur];
            float c[2][3][2][4];
#pragma unroll
            for (int mt = 0; mt < 2; mt++)
#pragma unroll
                for (int g = 0; g < 3; g++)
#pragma unroll
                    for (int nt = 0; nt < 2; nt++)
#pragma unroll
                        for (int q = 0; q < 4; q++) c[mt][g][nt][q] = 0.f;
#define LOADA1(HB, KK) do { \
            cpa16(HB + arow * 40 + aseg * 8, Ah + (size_t)(m0p1 + arow) * HID + (KK) + aseg * 8); \
            cpa16(HB + (arow + 64) * 40 + aseg * 8, Ah + (size_t)(m0p1 + arow + 64) * HID + (KK) + aseg * 8); } while (0)
#define LOADW(HB, KK, WP) do { \
            cpa16(HB + arow * 40 + aseg * 8, WP + (size_t)((arow >> 5) * HID + jb + (arow & 31)) * HID + (KK) + aseg * 8); \
            if (tid < 128) { int r2 = 64 + arow; \
                cpa16(HB + r2 * 40 + aseg * 8, WP + (size_t)((r2 >> 5) * HID + jb + (r2 & 31)) * HID + (KK) + aseg * 8); } } while (0)
            LOADA1(sAh0, 0); LOADW(sWh0, 0, Wp1); cpcommit();
            for (int ck = 0; ck < 32; ck++) {
                int buf = ck & 1;
                if (ck < 31) {
                    if (buf == 0) { LOADA1(sAh1, (ck + 1) * 32); LOADW(sWh1, (ck + 1) * 32, Wp1); }
                    else          { LOADA1(sAh0, (ck + 1) * 32); LOADW(sWh0, (ck + 1) * 32, Wp1); }
                    cpcommit(); cpwait1();
                } else cpwait0();
                __syncthreads();
                const unsigned* AU = sA[buf];
                const unsigned* WU = sW[buf];
#pragma unroll
                for (int ks = 0; ks < 2; ks++) {
                    unsigned a[2][4];
#pragma unroll
                    for (int mt = 0; mt < 2; mt++) {
                        int row = warpM * 32 + mt * 16 + g8;
                        a[mt][0] = AU[row * 20 + ks * 8 + t4];
                        a[mt][1] = AU[(row + 8) * 20 + ks * 8 + t4];
                        a[mt][2] = AU[row * 20 + ks * 8 + 4 + t4];
                        a[mt][3] = AU[(row + 8) * 20 + ks * 8 + 4 + t4];
                    }
#pragma unroll
                    for (int g = 0; g < 3; g++)
#pragma unroll
                        for (int nt = 0; nt < 2; nt++) {
                            unsigned b[2];
                            int rr = g * 32 + warpJ * 16 + nt * 8 + g8;
                            b[0] = WU[rr * 20 + ks * 8 + t4];
                            b[1] = WU[rr * 20 + ks * 8 + 4 + t4];
                            mmah(c[0][g][nt], a[0], b);
                            mmah(c[1][g][nt], a[1], b);
                        }
                }
                __syncthreads();
            }
            if (sel == 0) {
#pragma unroll
                for (int mt = 0; mt < 2; mt++)
#pragma unroll
                    for (int ci2 = 0; ci2 < 2; ci2++) {
                        int m = m0p1 + warpM * 32 + mt * 16 + g8 + ci2 * 8;
                        int tok = (t == 0) ? 0 : tgt[m * TT + t - 1];
                        const float* grow = g_G0 + (size_t)tok * H3;
#pragma unroll
                        for (int nt = 0; nt < 2; nt++)
#pragma unroll
                            for (int e = 0; e < 2; e++) {
                                int j = jb + warpJ * 16 + nt * 8 + t4 * 2 + e;
                                int ci = ci2 * 2 + e;
                                float r = sigm(grow[j] + c[mt][0][nt][ci] + bh[j]);
                                float z = sigm(grow[HID + j] + c[mt][1][nt][ci] + bh[HID + j]);
                                float n = tanhf(grow[2 * HID + j] + r * (c[mt][2][nt][ci] + bh[2 * HID + j]));
                                float hp = g_h0[cur][m * HID + j];
                                float hn = (1.0f - z) * n + z * hp;
                                g_h0[nxt][m * HID + j] = hn;
                                g_h0h[nxt][m * HID + j] = __float2half_rn(hn);
                            }
                    }
            } else {
#pragma unroll
                for (int mt = 0; mt < 2; mt++)
#pragma unroll
                    for (int ci2 = 0; ci2 < 2; ci2++) {
                        int m = m0p1 + warpM * 32 + mt * 16 + g8 + ci2 * 8;
#pragma unroll
                        for (int g = 0; g < 3; g++)
#pragma unroll
                            for (int nt = 0; nt < 2; nt++)
#pragma unroll
                                for (int e = 0; e < 2; e++) {
                                    int j = jb + warpJ * 16 + nt * 8 + t4 * 2 + e;
                                    g_gh1[m * H3 + g * HID + j] = c[mt][g][nt][ci2 * 2 + e] + bh[g * HID + j];
                                }
                    }
            }
        }
        gbarrier();
        // ===== phase 2 =====
        {
            const __half* Ah = g_h0h[nxt];
            float c2[3][2][4];
#pragma unroll
            for (int g = 0; g < 3; g++)
#pragma unroll
                for (int nt = 0; nt < 2; nt++)
#pragma unroll
                    for (int q = 0; q < 4; q++) c2[g][nt][q] = 0.f;
#define LOADA2(HB, KK) cpa16(HB + arow * 40 + aseg * 8, Ah + (size_t)(m0p2 + arow) * HID + (KK) + aseg * 8)
            LOADA2(sAh0, 0); LOADW(sWh0, 0, g_Wih1_h); cpcommit();
            for (int ck = 0; ck < 32; ck++) {
                int buf = ck & 1;
                if (ck < 31) {
                    if (buf == 0) { LOADA2(sAh1, (ck + 1) * 32); LOADW(sWh1, (ck + 1) * 32, g_Wih1_h); }
                    else          { LOADA2(sAh0, (ck + 1) * 32); LOADW(sWh0, (ck + 1) * 32, g_Wih1_h); }
                    cpcommit(); cpwait1();
                } else cpwait0();
                __syncthreads();
                const unsigned* AU = sA[buf];
                const unsigned* WU = sW[buf];
#pragma unroll
                for (int ks = 0; ks < 2; ks++) {
                    unsigned a[4];
                    int row = warpM * 16 + g8;
                    a[0] = AU[row * 20 + ks * 8 + t4];
                    a[1] = AU[(row + 8) * 20 + ks * 8 + t4];
                    a[2] = AU[row * 20 + ks * 8 + 4 + t4];
                    a[3] = AU[(row + 8) * 20 + ks * 8 + 4 + t4];
#pragma unroll
                    for (int g = 0; g < 3; g++)
#pragma unroll
                        for (int nt = 0; nt < 2; nt++) {
                            unsigned b[2];
                            int rr = g * 32 + warpJ * 16 + nt * 8 + g8;
                            b[0] = WU[rr * 20 + ks * 8 + t4];
                            b[1] = WU[rr * 20 + ks * 8 + 4 + t4];
                            mmah(c2[g][nt], a, b);
                        }
                }
                __syncthreads();
            }
#pragma unroll
            for (int ci2 = 0; ci2 < 2; ci2++) {
                int m = m0p2 + warpM * 16 + g8 + ci2 * 8;
#pragma unroll
                for (int nt = 0; nt < 2; nt++)
#pragma unroll
                    for (int e = 0; e < 2; e++) {
                        int j = jb + warpJ * 16 + nt * 8 + t4 * 2 + e;
                        int ci = ci2 * 2 + e;
                        float r = sigm(c2[0][nt][ci] + bi1[j] + ldcg(&g_gh1[m * H3 + j]));
                        float z = sigm(c2[1][nt][ci] + bi1[HID + j] + ldcg(&g_gh1[m * H3 + HID + j]));
                        float n = tanhf(c2[2][nt][ci] + bi1[2 * HID + j] + r * ldcg(&g_gh1[m * H3 + 2 * HID + j]));
                        float hp = g_h1[cur][m * HID + j];
                        float hn = (1.0f - z) * n + z * hp;
                        g_h1[nxt][m * HID + j] = hn;
                        __half hnh = __float2half_rn(hn);
                        g_h1h[nxt][m * HID + j] = hnh;
                        g_Hbufh[(size_t)t * BATCH * HID + (size_t)m * HID + j] = hnh;
                    }
            }
        }
        gbarrier();
    }
}

// ---------------- deferred fp16 output projection ----------------
// logits[(t*B+b), v] tile 128m x 64n, BK=32, double-buffered
__global__ __launch_bounds__(256) void k_logits16(const float* __restrict__ bo, float* __restrict__ out) {
    __shared__ __align__(16) unsigned sA[2][128 * 20];
    __shared__ __align__(16) unsigned sB[2][64 * 20];
    const int tid = threadIdx.x, lane = tid & 31, wid = tid >> 5;
    const int t4 = lane & 3, g8 = lane >> 2;
    const int warpM = wid & 3, warpN = wid >> 2;
    const int m0 = blockIdx.y * 128, n0 = blockIdx.x * 64;
    const int arow = tid >> 2, aseg = tid & 3;
    const __half* Ah = g_Hbufh;
    __half* sAh[2] = { (__half*)&sA[0][0], (__half*)&sA[1][0] };
    __half* sBh[2] = { (__half*)&sB[0][0], (__half*)&sB[1][0] };
    float c[2][4][4];
#pragma unroll
    for (int i = 0; i < 2; i++)
#pragma unroll
        for (int j = 0; j < 4; j++)
#pragma unroll
            for (int q = 0; q < 4; q++) c[i][j][q] = 0.f;
#define LOADL(BF, KK) do { \
    cpa16(sAh[BF] + arow * 40 + aseg * 8, Ah + (size_t)(m0 + arow) * HID + (KK) + aseg * 8); \
    cpa16(sAh[BF] + (arow + 64) * 40 + aseg * 8, Ah + (size_t)(m0 + arow + 64) * HID + (KK) + aseg * 8); \
    cpa16(sBh[BF] + arow * 40 + aseg * 8, g_Wo_h + (size_t)(n0 + arow) * HID + (KK) + aseg * 8); } while (0)
    LOADL(0, 0); cpcommit();
    for (int ck = 0; ck < 32; ck++) {
        int buf = ck & 1;
        if (ck < 31) { LOADL(buf ^ 1, (ck + 1) * 32); cpcommit(); cpwait1(); }
        else cpwait0();
        __syncthreads();
        const unsigned* AU = sA[buf];
        const unsigned* BU = sB[buf];
#pragma unroll
        for (int ks = 0; ks < 2; ks++) {
            unsigned a[2][4];
#pragma unroll
            for (int mt = 0; mt < 2; mt++) {
                int row = warpM * 32 + mt * 16 + g8;
                a[mt][0] = AU[row * 20 + ks * 8 + t4];
                a[mt][1] = AU[(row + 8) * 20 + ks * 8 + t4];
                a[mt][2] = AU[row * 20 + ks * 8 + 4 + t4];
                a[mt][3] = AU[(row + 8) * 20 + ks * 8 + 4 + t4];
            }
#pragma unroll
            for (int nt = 0; nt < 4; nt++) {
                unsigned b[2];
                int rr = warpN * 32 + nt * 8 + g8;
                b[0] = BU[rr * 20 + ks * 8 + t4];
                b[1] = BU[rr * 20 + ks * 8 + 4 + t4];
                mmah(c[0][nt], a[0], b);
                mmah(c[1][nt], a[1], b);
            }
        }
        __syncthreads();
    }
#pragma unroll
    for (int mt = 0; mt < 2; mt++)
#pragma unroll
        for (int nt = 0; nt < 4; nt++)
#pragma unroll
            for (int ci = 0; ci < 4; ci++) {
                int m = m0 + warpM * 32 + mt * 16 + g8 + ((ci & 2) ? 8 : 0);
                int n = n0 + warpN * 32 + nt * 8 + t4 * 2 + (ci & 1);
                int bb = m & (BATCH - 1), tt = m >> 8;
                out[((size_t)bb * TT + tt) * VOC + n] = c[mt][nt][ci] + bo[n];
            }
}

__global__ __launch_bounds__(128) void k_lsm(float* out) {
    float* p = out + (size_t)blockIdx.x * VOC;
    const int tid = threadIdx.x, lane = tid & 31, wid = tid >> 5;
    __shared__ float smx[4], ssm[4];
    float v[4];
#pragma unroll
    for (int i = 0; i < 4; i++) v[i] = p[tid + 128 * i];
    float mx = fmaxf(fmaxf(v[0], v[1]), fmaxf(v[2], v[3]));
#pragma unroll
    for (int o = 16; o; o >>= 1) mx = fmaxf(mx, __shfl_xor_sync(0xffffffffu, mx, o));
    if (lane == 0) smx[wid] = mx;
    __syncthreads();
    mx = fmaxf(fmaxf(smx[0], smx[1]), fmaxf(smx[2], smx[3]));
    float s = 0.f;
#pragma unroll
    for (int i = 0; i < 4; i++) s += __expf(v[i] - mx);
#pragma unroll
    for (int o = 16; o; o >>= 1) s += __shfl_xor_sync(0xffffffffu, s, o);
    if (lane == 0) ssm[wid] = s;
    __syncthreads();
    s = ssm[0] + ssm[1] + ssm[2] + ssm[3];
    float lse = mx + logf(s);
#pragma unroll
    for (int i = 0; i < 4; i++) p[tid + 128 * i] = v[i] - lse;
}

__global__ __launch_bounds__(512) void k_hfinal(float* outh) {
    int i = blockIdx.x * blockDim.x + threadIdx.x;
    if (i < BATCH * HID) outh[i] = g_h0[0][i];
    else outh[i] = g_h1[0][i - BATCH * HID];
}

// ---------------- launch ----------------
extern "C" void kernel_launch(void* const* d_in, const int* in_sizes, int n_in,
                              void* d_out, int out_size) {
    (void)in_sizes; (void)n_in; (void)out_size;
    const float* fp   = (const float*)d_in[1];
    const int*   tgt  = (const int*)d_in[2];
    const float* emb  = (const float*)d_in[3];
    const float* Wc   = (const float*)d_in[4];
    const float* bc   = (const float*)d_in[5];
    const float* W_ih = (const float*)d_in[6];
    const float* W_hh = (const float*)d_in[7];
    const float* b_ih = (const float*)d_in[8];
    const float* b_hh = (const float*)d_in[9];
    const float* Wo   = (const float*)d_in[10];
    const float* bo   = (const float*)d_in[11];
    float* out = (float*)d_out;

    k_init_h0<<<dim3(16, 4), 256>>>(fp, Wc, bc);
    k_init_G0<<<dim3(48, 8), 256>>>(emb, W_ih, b_ih);
    k_convW<<<1024, 256>>>(W_hh, W_ih, Wo);
    k_loop<<<NB, 256>>>(tgt, b_ih, b_hh);
    k_logits16<<<dim3(8, 512), 256>>>(bo, out);
    k_lsm<<<65536, 128>>>(out);
    k_hfinal<<<1024, 512>>>(out + (size_t)BATCH * TT * VOC);
}

// round 4
// speedup vs baseline: 2.3238x; 1.2716x over previous
#include <cuda_runtime.h>
#include <cuda_fp16.h>
#include <math.h>

#define BATCH 256
#define HID   1024
#define H3    3072
#define VOC   512
#define TT    256
#define FPD   2048
#define WH    (H3 * HID)
#define NB    128

// ---------------- device scratch ----------------
__device__ __align__(256) float  g_h0[2][BATCH * HID];
__device__ __align__(256) float  g_h1[2][BATCH * HID];
__device__ __align__(256) __half g_h0h[2][BATCH * HID];
__device__ __align__(256) __half g_h1h[2][BATCH * HID];
__device__ __align__(256) float  g_G0[VOC * H3];
__device__ __align__(256) float  g_gh1[BATCH * H3];
__device__ __align__(256) __half g_Whh_h[2][WH];
__device__ __align__(256) __half g_Wih1_h[WH];
__device__ __align__(256) __half g_Wo_h[VOC * HID];
__device__ __align__(256) __half g_Hbufh[(size_t)TT * BATCH * HID];
__device__ unsigned g_bar_count = 0;
__device__ unsigned g_bar_gen   = 0;

// ---------------- helpers ----------------
__device__ __forceinline__ unsigned f2tf(float f) {
    unsigned u; asm("cvt.rna.tf32.f32 %0, %1;" : "=r"(u) : "f"(f)); return u;
}
__device__ __forceinline__ void mma8(float c[4], const unsigned a[4], const unsigned b[2]) {
    asm volatile("mma.sync.aligned.m16n8k8.row.col.f32.tf32.tf32.f32 "
                 "{%0,%1,%2,%3},{%4,%5,%6,%7},{%8,%9},{%0,%1,%2,%3};"
                 : "+f"(c[0]), "+f"(c[1]), "+f"(c[2]), "+f"(c[3])
                 : "r"(a[0]), "r"(a[1]), "r"(a[2]), "r"(a[3]), "r"(b[0]), "r"(b[1]));
}
__device__ __forceinline__ void mmah(float c[4], const unsigned a[4], const unsigned b[2]) {
    asm volatile("mma.sync.aligned.m16n8k16.row.col.f32.f16.f16.f32 "
                 "{%0,%1,%2,%3},{%4,%5,%6,%7},{%8,%9},{%0,%1,%2,%3};"
                 : "+f"(c[0]), "+f"(c[1]), "+f"(c[2]), "+f"(c[3])
                 : "r"(a[0]), "r"(a[1]), "r"(a[2]), "r"(a[3]), "r"(b[0]), "r"(b[1]));
}
__device__ __forceinline__ void ldsm4(unsigned r[4], const __half* p) {
    unsigned a = (unsigned)__cvta_generic_to_shared(p);
    asm volatile("ldmatrix.sync.aligned.m8n8.x4.shared.b16 {%0,%1,%2,%3},[%4];"
                 : "=r"(r[0]), "=r"(r[1]), "=r"(r[2]), "=r"(r[3]) : "r"(a));
}
__device__ __forceinline__ void ldsm2(unsigned r[2], const __half* p) {
    unsigned a = (unsigned)__cvta_generic_to_shared(p);
    asm volatile("ldmatrix.sync.aligned.m8n8.x2.shared.b16 {%0,%1},[%2];"
                 : "=r"(r[0]), "=r"(r[1]) : "r"(a));
}
__device__ __forceinline__ float sigm(float x) { return 1.0f / (1.0f + __expf(-x)); }
__device__ __forceinline__ void cpa16(const __half* dst, const __half* src) {
    unsigned d = (unsigned)__cvta_generic_to_shared(dst);
    asm volatile("cp.async.cg.shared.global [%0], [%1], 16;" :: "r"(d), "l"(src));
}
__device__ __forceinline__ void cpcommit() { asm volatile("cp.async.commit_group;"); }
__device__ __forceinline__ void cpwait1()  { asm volatile("cp.async.wait_group 1;"); }
__device__ __forceinline__ void cpwait0()  { asm volatile("cp.async.wait_group 0;"); }
__device__ __forceinline__ float ldcg(const float* p) {
    float v; asm volatile("ld.global.cg.f32 %0, [%1];" : "=f"(v) : "l"(p)); return v;
}
__device__ __forceinline__ void gbarrier() {
    __threadfence();
    __syncthreads();
    if (threadIdx.x == 0) {
        unsigned gen = *((volatile unsigned*)&g_bar_gen);
        if (atomicAdd(&g_bar_count, 1u) == NB - 1) {
            g_bar_count = 0;
            __threadfence();
            atomicAdd(&g_bar_gen, 1u);
        } else {
            while (*((volatile unsigned*)&g_bar_gen) == gen) { __nanosleep(16); }
        }
    }
    __syncthreads();
}

// ---------------- tf32 64x64 GEMM (init kernels only) ----------------
__device__ __forceinline__ void gemm64x64(const float* A, int lda, const float* W, int ldw,
                                          int K, int m0, int n0, int reluA,
                                          unsigned* As, unsigned* Bs, float c[2][2][4]) {
    const int tid = threadIdx.x, lane = tid & 31, wid = tid >> 5;
    const int g = lane >> 2, t4 = lane & 3;
    const int warpM = wid >> 2, warpN = wid & 3;
    for (int kk = 0; kk < K; kk += 32) {
#pragma unroll
        for (int p = 0; p < 2; p++) {
            int r = p * 32 + (tid >> 3), c4 = (tid & 7) * 4;
            float4 v = *(const float4*)(A + (size_t)(m0 + r) * lda + kk + c4);
            if (reluA) { v.x = fmaxf(v.x, 0.f); v.y = fmaxf(v.y, 0.f); v.z = fmaxf(v.z, 0.f); v.w = fmaxf(v.w, 0.f); }
            unsigned* d = As + r * 36 + c4;
            d[0] = f2tf(v.x); d[1] = f2tf(v.y); d[2] = f2tf(v.z); d[3] = f2tf(v.w);
            float4 w = *(const float4*)(W + (size_t)(n0 + r) * ldw + kk + c4);
            unsigned* e = Bs + r * 36 + c4;
            e[0] = f2tf(w.x); e[1] = f2tf(w.y); e[2] = f2tf(w.z); e[3] = f2tf(w.w);
        }
        __syncthreads();
#pragma unroll
        for (int ks = 0; ks < 4; ks++) {
            int kb = ks * 8;
            unsigned a[2][4], b[2][2];
#pragma unroll
            for (int mt = 0; mt < 2; mt++) {
                int row = warpM * 32 + mt * 16 + g;
                a[mt][0] = As[row * 36 + kb + t4];
                a[mt][1] = As[(row + 8) * 36 + kb + t4];
                a[mt][2] = As[row * 36 + kb + t4 + 4];
                a[mt][3] = As[(row + 8) * 36 + kb + t4 + 4];
            }
#pragma unroll
            for (int nt = 0; nt < 2; nt++) {
                int nr = warpN * 16 + nt * 8 + g;
                b[nt][0] = Bs[nr * 36 + kb + t4];
                b[nt][1] = Bs[nr * 36 + kb + t4 + 4];
            }
#pragma unroll
            for (int mt = 0; mt < 2; mt++)
#pragma unroll
                for (int nt = 0; nt < 2; nt++) mma8(c[mt][nt], a[mt], b[nt]);
        }
        __syncthreads();
    }
}

__global__ __launch_bounds__(256) void k_init_h0(const float* fp, const float* Wc, const float* bc) {
    __shared__ unsigned As[64 * 36], Bs[64 * 36];
    float c[2][2][4] = {};
    int n0 = blockIdx.x * 64, m0 = blockIdx.y * 64;
    gemm64x64(fp, FPD, Wc, FPD, FPD, m0, n0, 0, As, Bs, c);
    const int tid = threadIdx.x, lane = tid & 31, wid = tid >> 5;
    const int g = lane >> 2, t4 = lane & 3;
    const int warpM = wid >> 2, warpN = wid & 3;
#pragma unroll
    for (int mt = 0; mt < 2; mt++)
#pragma unroll
        for (int nt = 0; nt < 2; nt++)
#pragma unroll
            for (int ci = 0; ci < 4; ci++) {
                int m = m0 + warpM * 32 + mt * 16 + g + ((ci & 2) ? 8 : 0);
                int n = n0 + warpN * 16 + nt * 8 + t4 * 2 + (ci & 1);
                float v = fmaxf(c[mt][nt][ci] + bc[n], 0.f);
                g_h0[0][m * HID + n] = v;
                g_h1[0][m * HID + n] = v;
                __half vh = __float2half_rn(v);
                g_h0h[0][m * HID + n] = vh;
                g_h1h[0][m * HID + n] = vh;
            }
}

__global__ __launch_bounds__(256) void k_init_G0(const float* emb, const float* Wih, const float* bih) {
    __shared__ unsigned As[64 * 36], Bs[64 * 36];
    float c[2][2][4] = {};
    int n0 = blockIdx.x * 64, m0 = blockIdx.y * 64;
    gemm64x64(emb, HID, Wih, HID, HID, m0, n0, 1, As, Bs, c);
    const int tid = threadIdx.x, lane = tid & 31, wid = tid >> 5;
    const int g = lane >> 2, t4 = lane & 3;
    const int warpM = wid >> 2, warpN = wid & 3;
#pragma unroll
    for (int mt = 0; mt < 2; mt++)
#pragma unroll
        for (int nt = 0; nt < 2; nt++)
#pragma unroll
            for (int ci = 0; ci < 4; ci++) {
                int m = m0 + warpM * 32 + mt * 16 + g + ((ci & 2) ? 8 : 0);
                int n = n0 + warpN * 16 + nt * 8 + t4 * 2 + (ci & 1);
                g_G0[m * H3 + n] = c[mt][nt][ci] + bih[n];
            }
}

__global__ __launch_bounds__(256) void k_convW(const float* Whh, const float* Wih, const float* Wo) {
    size_t i = (size_t)blockIdx.x * blockDim.x + threadIdx.x;
    size_t stride = (size_t)gridDim.x * blockDim.x;
    __half* whh = &g_Whh_h[0][0];
    for (size_t k = i; k < 2 * (size_t)WH; k += stride) whh[k] = __float2half_rn(Whh[k]);
    for (size_t k = i; k < (size_t)WH; k += stride) g_Wih1_h[k] = __float2half_rn(Wih[WH + k]);
    for (size_t k = i; k < (size_t)VOC * HID; k += stride) g_Wo_h[k] = __float2half_rn(Wo[k]);
}

// ---------------- persistent recurrent kernel (v2: 512thr, ldmatrix, 3-stage) ----------------
#define ASTRIDE 40
#define A_ST (128 * ASTRIDE)
#define W_ST (96 * ASTRIDE)
#define KLOOP_SMEM ((3 * (A_ST + W_ST)) * 2)

__global__ __launch_bounds__(512, 1) void k_loop(const int* __restrict__ tgt,
                                                 const float* __restrict__ b_ih,
                                                 const float* __restrict__ b_hh) {
    extern __shared__ __align__(16) __half dyn[];
    __half* sA = dyn;                 // [3][128][ASTRIDE]
    __half* sW = dyn + 3 * A_ST;      // [3][96][ASTRIDE]
    const int tid = threadIdx.x, lane = tid & 31, wid = tid >> 5;
    const int g8 = lane >> 2, t4 = lane & 3;
    const int warpM = wid & 3, warpJ = wid >> 2;       // 4 x 4 warps
    const int bid = blockIdx.x;
    const int sel = bid >> 6;
    const int m0p1 = ((bid >> 5) & 1) * 128;
    const int m0p2 = (bid >> 5) * 64;
    const int jb = (bid & 31) * 32;
    const float* bh  = b_hh + sel * H3;
    const float* bi1 = b_ih + H3;
    const __half* Wp1 = g_Whh_h[sel];
    // ldmatrix lane addressing
    const int l15 = lane & 15;
    const int aRow = l15, aK = (lane >> 4) * 8;            // A: x4
    const int bRow = l15 & 7, bK = ((l15 >> 3) & 1) * 8;   // B: x2
    // cp.async thread mapping
    const int crow = tid >> 2, cseg = (tid & 3) * 8;

#define SAp(S, R, C) (sA + ((S) * 128 + (R)) * ASTRIDE + (C))
#define SWp(S, R, C) (sW + ((S) * 96 + (R)) * ASTRIDE + (C))
#define LA1(S, KK) cpa16(SAp(S, crow, cseg), Ah + (size_t)(m0p1 + crow) * HID + (KK) + cseg)
#define LA2(S, KK) do { if (tid < 256) cpa16(SAp(S, crow, cseg), Ah + (size_t)(m0p2 + crow) * HID + (KK) + cseg); } while (0)
#define LW(S, KK, WP) do { if (tid < 384) \
    cpa16(SWp(S, crow, cseg), (WP) + (size_t)((crow >> 5) * HID + jb + (crow & 31)) * HID + (KK) + cseg); } while (0)

    for (int t = 0; t < TT; t++) {
        const int cur = t & 1, nxt = cur ^ 1;
        // ================= phase 1: 128m x (3g x 32j), K=1024 =================
        {
            const __half* Ah = sel ? g_h1h[cur] : g_h0h[cur];
            float c[2][3][4];
#pragma unroll
            for (int mt = 0; mt < 2; mt++)
#pragma unroll
                for (int g = 0; g < 3; g++)
#pragma unroll
                    for (int q = 0; q < 4; q++) c[mt][g][q] = 0.f;

            LA1(0, 0);  LW(0, 0, Wp1);  cpcommit();
            LA1(1, 32); LW(1, 32, Wp1); cpcommit();
            for (int ck = 0; ck < 32; ck++) {
                if (ck < 31) cpwait1(); else cpwait0();
                __syncthreads();
                if (ck + 2 < 32) {
                    int sn = (ck + 2) % 3, kk = (ck + 2) * 32;
                    LA1(sn, kk); LW(sn, kk, Wp1);
                }
                cpcommit();
                const int s = ck % 3;
#pragma unroll
                for (int ks = 0; ks < 2; ks++) {
                    unsigned a0[4], a1[4];
                    ldsm4(a0, SAp(s, warpM * 32 + aRow,      ks * 16 + aK));
                    ldsm4(a1, SAp(s, warpM * 32 + 16 + aRow, ks * 16 + aK));
#pragma unroll
                    for (int g = 0; g < 3; g++) {
                        unsigned b[2];
                        ldsm2(b, SWp(s, g * 32 + warpJ * 8 + bRow, ks * 16 + bK));
                        mmah(c[0][g], a0, b);
                        mmah(c[1][g], a1, b);
                    }
                }
            }
            if (sel == 0) {
#pragma unroll
                for (int mt = 0; mt < 2; mt++)
#pragma unroll
                    for (int ci2 = 0; ci2 < 2; ci2++) {
                        int m = m0p1 + warpM * 32 + mt * 16 + g8 + ci2 * 8;
                        int tok = (t == 0) ? 0 : tgt[m * TT + t - 1];
                        const float* grow = g_G0 + (size_t)tok * H3;
#pragma unroll
                        for (int e = 0; e < 2; e++) {
                            int j = jb + warpJ * 8 + t4 * 2 + e;
                            int ci = ci2 * 2 + e;
                            float r = sigm(grow[j] + c[mt][0][ci] + bh[j]);
                            float z = sigm(grow[HID + j] + c[mt][1][ci] + bh[HID + j]);
                            float n = tanhf(grow[2 * HID + j] + r * (c[mt][2][ci] + bh[2 * HID + j]));
                            float hp = g_h0[cur][m * HID + j];
                            float hn = (1.0f - z) * n + z * hp;
                            g_h0[nxt][m * HID + j] = hn;
                            g_h0h[nxt][m * HID + j] = __float2half_rn(hn);
                        }
                    }
            } else {
#pragma unroll
                for (int mt = 0; mt < 2; mt++)
#pragma unroll
                    for (int ci2 = 0; ci2 < 2; ci2++) {
                        int m = m0p1 + warpM * 32 + mt * 16 + g8 + ci2 * 8;
#pragma unroll
                        for (int g = 0; g < 3; g++)
#pragma unroll
                            for (int e = 0; e < 2; e++) {
                                int j = jb + warpJ * 8 + t4 * 2 + e;
                                g_gh1[m * H3 + g * HID + j] = c[mt][g][ci2 * 2 + e] + bh[g * HID + j];
                            }
                    }
            }
        }
        gbarrier();
        // ================= phase 2: 64m x (3g x 32j), K=1024 =================
        {
            const __half* Ah = g_h0h[nxt];
            float c2[3][4];
#pragma unroll
            for (int g = 0; g < 3; g++)
#pragma unroll
                for (int q = 0; q < 4; q++) c2[g][q] = 0.f;

            LA2(0, 0);  LW(0, 0, g_Wih1_h);  cpcommit();
            LA2(1, 32); LW(1, 32, g_Wih1_h); cpcommit();
            for (int ck = 0; ck < 32; ck++) {
                if (ck < 31) cpwait1(); else cpwait0();
                __syncthreads();
                if (ck + 2 < 32) {
                    int sn = (ck + 2) % 3, kk = (ck + 2) * 32;
                    LA2(sn, kk); LW(sn, kk, g_Wih1_h);
                }
                cpcommit();
                const int s = ck % 3;
#pragma unroll
                for (int ks = 0; ks < 2; ks++) {
                    unsigned a0[4];
                    ldsm4(a0, SAp(s, warpM * 16 + aRow, ks * 16 + aK));
#pragma unroll
                    for (int g = 0; g < 3; g++) {
                        unsigned b[2];
                        ldsm2(b, SWp(s, g * 32 + warpJ * 8 + bRow, ks * 16 + bK));
                        mmah(c2[g], a0, b);
                    }
                }
            }
#pragma unroll
            for (int ci2 = 0; ci2 < 2; ci2++) {
                int m = m0p2 + warpM * 16 + g8 + ci2 * 8;
#pragma unroll
                for (int e = 0; e < 2; e++) {
                    int j = jb + warpJ * 8 + t4 * 2 + e;
                    int ci = ci2 * 2 + e;
                    float r = sigm(c2[0][ci] + bi1[j] + ldcg(&g_gh1[m * H3 + j]));
                    float z = sigm(c2[1][ci] + bi1[HID + j] + ldcg(&g_gh1[m * H3 + HID + j]));
                    float n = tanhf(c2[2][ci] + bi1[2 * HID + j] + r * ldcg(&g_gh1[m * H3 + 2 * HID + j]));
                    float hp = g_h1[cur][m * HID + j];
                    float hn = (1.0f - z) * n + z * hp;
                    g_h1[nxt][m * HID + j] = hn;
                    __half hnh = __float2half_rn(hn);
                    g_h1h[nxt][m * HID + j] = hnh;
                    g_Hbufh[(size_t)t * BATCH * HID + (size_t)m * HID + j] = hnh;
                }
            }
        }
        gbarrier();
    }
}

// ---------------- deferred fp16 output projection ----------------
__global__ __launch_bounds__(256) void k_logits16(const float* __restrict__ bo, float* __restrict__ out) {
    __shared__ __align__(16) unsigned sA[2][128 * 20];
    __shared__ __align__(16) unsigned sB[2][64 * 20];
    const int tid = threadIdx.x, lane = tid & 31, wid = tid >> 5;
    const int t4 = lane & 3, g8 = lane >> 2;
    const int warpM = wid & 3, warpN = wid >> 2;
    const int m0 = blockIdx.y * 128, n0 = blockIdx.x * 64;
    const int arow = tid >> 2, aseg = tid & 3;
    const __half* Ah = g_Hbufh;
    __half* sAh[2] = { (__half*)&sA[0][0], (__half*)&sA[1][0] };
    __half* sBh[2] = { (__half*)&sB[0][0], (__half*)&sB[1][0] };
    float c[2][4][4];
#pragma unroll
    for (int i = 0; i < 2; i++)
#pragma unroll
        for (int j = 0; j < 4; j++)
#pragma unroll
            for (int q = 0; q < 4; q++) c[i][j][q] = 0.f;
#define LOADL(BF, KK) do { \
    cpa16(sAh[BF] + arow * 40 + aseg * 8, Ah + (size_t)(m0 + arow) * HID + (KK) + aseg * 8); \
    cpa16(sAh[BF] + (arow + 64) * 40 + aseg * 8, Ah + (size_t)(m0 + arow + 64) * HID + (KK) + aseg * 8); \
    cpa16(sBh[BF] + arow * 40 + aseg * 8, g_Wo_h + (size_t)(n0 + arow) * HID + (KK) + aseg * 8); } while (0)
    LOADL(0, 0); cpcommit();
    for (int ck = 0; ck < 32; ck++) {
        int buf = ck & 1;
        if (ck < 31) { LOADL(buf ^ 1, (ck + 1) * 32); cpcommit(); cpwait1(); }
        else cpwait0();
        __syncthreads();
        const unsigned* AU = sA[buf];
        const unsigned* BU = sB[buf];
#pragma unroll
        for (int ks = 0; ks < 2; ks++) {
            unsigned a[2][4];
#pragma unroll
            for (int mt = 0; mt < 2; mt++) {
                int row = warpM * 32 + mt * 16 + g8;
                a[mt][0] = AU[row * 20 + ks * 8 + t4];
                a[mt][1] = AU[(row + 8) * 20 + ks * 8 + t4];
                a[mt][2] = AU[row * 20 + ks * 8 + 4 + t4];
                a[mt][3] = AU[(row + 8) * 20 + ks * 8 + 4 + t4];
            }
#pragma unroll
            for (int nt = 0; nt < 4; nt++) {
                unsigned b[2];
                int rr = warpN * 32 + nt * 8 + g8;
                b[0] = BU[rr * 20 + ks * 8 + t4];
                b[1] = BU[rr * 20 + ks * 8 + 4 + t4];
                mmah(c[0][nt], a[0], b);
                mmah(c[1][nt], a[1], b);
            }
        }
        __syncthreads();
    }
#pragma unroll
    for (int mt = 0; mt < 2; mt++)
#pragma unroll
        for (int nt = 0; nt < 4; nt++)
#pragma unroll
            for (int ci = 0; ci < 4; ci++) {
                int m = m0 + warpM * 32 + mt * 16 + g8 + ((ci & 2) ? 8 : 0);
                int n = n0 + warpN * 32 + nt * 8 + t4 * 2 + (ci & 1);
                int bb = m & (BATCH - 1), tt = m >> 8;
                out[((size_t)bb * TT + tt) * VOC + n] = c[mt][nt][ci] + bo[n];
            }
}

__global__ __launch_bounds__(128) void k_lsm(float* out) {
    float* p = out + (size_t)blockIdx.x * VOC;
    const int tid = threadIdx.x, lane = tid & 31, wid = tid >> 5;
    __shared__ float smx[4], ssm[4];
    float v[4];
#pragma unroll
    for (int i = 0; i < 4; i++) v[i] = p[tid + 128 * i];
    float mx = fmaxf(fmaxf(v[0], v[1]), fmaxf(v[2], v[3]));
#pragma unroll
    for (int o = 16; o; o >>= 1) mx = fmaxf(mx, __shfl_xor_sync(0xffffffffu, mx, o));
    if (lane == 0) smx[wid] = mx;
    __syncthreads();
    mx = fmaxf(fmaxf(smx[0], smx[1]), fmaxf(smx[2], smx[3]));
    float s = 0.f;
#pragma unroll
    for (int i = 0; i < 4; i++) s += __expf(v[i] - mx);
#pragma unroll
    for (int o = 16; o; o >>= 1) s += __shfl_xor_sync(0xffffffffu, s, o);
    if (lane == 0) ssm[wid] = s;
    __syncthreads();
    s = ssm[0] + ssm[1] + ssm[2] + ssm[3];
    float lse = mx + logf(s);
#pragma unroll
    for (int i = 0; i < 4; i++) p[tid + 128 * i] = v[i] - lse;
}

__global__ __launch_bounds__(512) void k_hfinal(float* outh) {
    int i = blockIdx.x * blockDim.x + threadIdx.x;
    if (i < BATCH * HID) outh[i] = g_h0[0][i];
    else outh[i] = g_h1[0][i - BATCH * HID];
}

// ---------------- launch ----------------
extern "C" void kernel_launch(void* const* d_in, const int* in_sizes, int n_in,
                              void* d_out, int out_size) {
    (void)in_sizes; (void)n_in; (void)out_size;
    const float* fp   = (const float*)d_in[1];
    const int*   tgt  = (const int*)d_in[2];
    const float* emb  = (const float*)d_in[3];
    const float* Wc   = (const float*)d_in[4];
    const float* bc   = (const float*)d_in[5];
    const float* W_ih = (const float*)d_in[6];
    const float* W_hh = (const float*)d_in[7];
    const float* b_ih = (const float*)d_in[8];
    const float* b_hh = (const float*)d_in[9];
    const float* Wo   = (const float*)d_in[10];
    const float* bo   = (const float*)d_in[11];
    float* out = (float*)d_out;

    cudaFuncSetAttribute(k_loop, cudaFuncAttributeMaxDynamicSharedMemorySize, KLOOP_SMEM);

    k_init_h0<<<dim3(16, 4), 256>>>(fp, Wc, bc);
    k_init_G0<<<dim3(48, 8), 256>>>(emb, W_ih, b_ih);
    k_convW<<<1024, 256>>>(W_hh, W_ih, Wo);
    k_loop<<<NB, 512, KLOOP_SMEM>>>(tgt, b_ih, b_hh);
    k_logits16<<<dim3(8, 512), 256>>>(bo, out);
    k_lsm<<<65536, 128>>>(out);
    k_hfinal<<<1024, 512>>>(out + (size_t)BATCH * TT * VOC);
}